// round 15
// baseline (speedup 1.0000x reference)
#include <cuda_runtime.h>
#include <cuda_bf16.h>
#include <math.h>

// Fixed shape: A=128 atoms, FR=16 partials, NS=32768 samples, NF=128 frames.
// t = 128*T + tau, T in [0,256), tau in [0,128).
// out[a, 128T+tau] = Ah*Ch + Al*Ch + Ah*Cl (hi/lo bf16 split; K-blocks of 64
// via address mapping). CTA = (atom, T-quarter): grid (128, 4) = 512 CTAs,
// one co-resident wave at 4 CTAs/SM. Fragment loads via ldmatrix.x4.
// Build loops are f-major within the warp with packed STS.64 -> conflict-free
// smem writes (was 8-way conflicted tau-major STS.32).
#define FR   16
#define NS   32768
#define TPB  256
#define PAD  136                    // bf16 per smem row (128+8); 68 words = 4 mod 32

#define TURN2RAD 1.4629180792671596e-9f   // 2*pi / 2^32

// smem layout (bytes)
#define SM_PAR 0                    // float4[16]
#define SM_A   256                  // bf16[128*136] = 34816  {Ah | Al}
#define SM_C   35072                // bf16[ 64*136] = 17408  {Ch | Cl}
#define SM_TOTAL 52480

typedef unsigned u32;

static __device__ __forceinline__ void mma16816(float* d, const u32* a, u32 b0, u32 b1) {
    asm volatile(
        "mma.sync.aligned.m16n8k16.row.col.f32.bf16.bf16.f32 "
        "{%0,%1,%2,%3}, {%4,%5,%6,%7}, {%8,%9}, {%0,%1,%2,%3};"
        : "+f"(d[0]), "+f"(d[1]), "+f"(d[2]), "+f"(d[3])
        : "r"(a[0]), "r"(a[1]), "r"(a[2]), "r"(a[3]), "r"(b0), "r"(b1));
}

static __device__ __forceinline__ void ldsm4(u32& r0, u32& r1, u32& r2, u32& r3, u32 addr) {
    asm volatile("ldmatrix.sync.aligned.m8n8.x4.shared.b16 {%0,%1,%2,%3}, [%4];"
                 : "=r"(r0), "=r"(r1), "=r"(r2), "=r"(r3) : "r"(addr));
}

// pack {bf16(a), bf16(b)} into a u32
static __device__ __forceinline__ u32 pkbf(float a, float b) {
    u32 r;
    asm("cvt.rn.bf16x2.f32 %0, %2, %1;" : "=r"(r) : "f"(a), "f"(b));
    return r;
}

// ---------------------------------------------------------------------------
__global__ void __launch_bounds__(TPB, 4)
synth_mma_kernel(const float* __restrict__ osc,
                 const float* __restrict__ amp,
                 const float* __restrict__ decay,
                 float* __restrict__ out)
{
    extern __shared__ char smem[];
    float4*        par = (float4*)(smem + SM_PAR);    // {phi bits, P, d, log2 d}
    __nv_bfloat16* As  = (__nv_bfloat16*)(smem + SM_A);
    __nv_bfloat16* Cs  = (__nv_bfloat16*)(smem + SM_C);

    const int tid = threadIdx.x;
    const int a   = blockIdx.x;
    const int nh  = blockIdx.y;                       // T-quarter: T = nh*64 + Tl

    // --- per-partial params (replicate reference fp32 rounding chain) ---
    if (tid < FR) {
        int i = a * FR + tid;
        float o   = osc[i];
        float sgf = (float)(1.0 / (1.0 + exp(-(double)o)));
        float fq  = (sgf * sgf) * 3.14159274101257324219f;     // fl32(pi)
        double f2p = (double)fq * (1.0 / (2.0 * M_PI));
        u32 phi = (u32)llrint(f2p * 4294967296.0);             // Q0.32 turns/sample

        float am = amp[i];
        float P  = am * am * 0.0625f;

        float dv  = decay[i];
        float sgd = (float)(1.0 / (1.0 + exp(-(double)dv)));
        float d   = 0.7f + sgd * 0.299999f;
        float l2d = (float)log2((double)d);
        par[tid] = make_float4(__uint_as_float(phi), P, d, l2d);
    }
    __syncthreads();

    // --- A (basis) tile {Ah | Al}: f-major items, packed STS.64, no conflicts ---
    for (int idx = tid; idx < FR * 128; idx += TPB) {
        int f = idx & 15, tau = idx >> 4;
        u32 phi = __float_as_uint(par[f].x);
        u32 p   = (u32)tau * phi;
        float x = (float)(int)p * TURN2RAD;
        float s = __sinf(x), c = __cosf(x);
        float ts = (float)tau * 0.0078125f;
        float v0 = s, v1 = c, v2 = s * ts, v3 = c * ts;

        u32 h01 = pkbf(v0, v1), h23 = pkbf(v2, v3);
        float r0 = v0 - __bfloat162float(__ushort_as_bfloat16((unsigned short)(h01 & 0xFFFF)));
        float r1 = v1 - __bfloat162float(__ushort_as_bfloat16((unsigned short)(h01 >> 16)));
        float r2 = v2 - __bfloat162float(__ushort_as_bfloat16((unsigned short)(h23 & 0xFFFF)));
        float r3 = v3 - __bfloat162float(__ushort_as_bfloat16((unsigned short)(h23 >> 16)));
        u32 l01 = pkbf(r0, r1), l23 = pkbf(r2, r3);

        __nv_bfloat16* row = As + tau * PAD + 4 * f;
        *(uint2*)(row)      = make_uint2(h01, h23);    // Ah (STS.64, 8B-aligned)
        *(uint2*)(row + 64) = make_uint2(l01, l23);    // Al
    }

    // --- C (coefficient) tile {Ch | Cl}: f-major, packed STS.64 ---
    for (int idx = tid; idx < FR * 64; idx += TPB) {
        int f = idx & 15, Tl = idx >> 4;
        int T = nh * 64 + Tl;
        float4 pr = par[f];
        u32 phi = __float_as_uint(pr.x);
        float P = pr.y, d = pr.z, l2d = pr.w;

        float al, be;
        if (T == 0)        { al = exp2f(l2d);          be = 0.0f; }
        else if (T == 255) { al = exp2f(128.0f * l2d); be = 0.0f; }
        else {
            int   i0 = (T - 1) >> 1;
            float w0 = (T & 1) ? 0.001953125f : 0.501953125f;
            float dj = exp2f((float)(i0 + 1) * l2d);   // d^(i0+1)
            float dm1 = d - 1.0f;
            al = dj * fmaf(w0, dm1, 1.0f);
            be = dj * dm1 * 0.5f;              // coefficient of ts = tau/128
        }
        u32 p   = (u32)(128 * T + 1) * phi;
        float x = (float)(int)p * TURN2RAD;
        float SA = __sinf(x), CA = __cosf(x);
        float Pal = P * al, Pbe = P * be;
        float e0 = Pal * CA, e1 = Pal * SA, e2 = Pbe * CA, e3 = Pbe * SA;

        u32 h01 = pkbf(e0, e1), h23 = pkbf(e2, e3);
        float r0 = e0 - __bfloat162float(__ushort_as_bfloat16((unsigned short)(h01 & 0xFFFF)));
        float r1 = e1 - __bfloat162float(__ushort_as_bfloat16((unsigned short)(h01 >> 16)));
        float r2 = e2 - __bfloat162float(__ushort_as_bfloat16((unsigned short)(h23 & 0xFFFF)));
        float r3 = e3 - __bfloat162float(__ushort_as_bfloat16((unsigned short)(h23 >> 16)));
        u32 l01 = pkbf(r0, r1), l23 = pkbf(r2, r3);

        __nv_bfloat16* row = Cs + Tl * PAD + 4 * f;
        *(uint2*)(row)      = make_uint2(h01, h23);    // Ch
        *(uint2*)(row + 64) = make_uint2(l01, l23);    // Cl
    }
    __syncthreads();

    // --- MMA: D[128 tau x 64 Tl]. warp = (mh tau-half, nw 16-T stripe). ---
    const int w    = tid >> 5, lane = tid & 31;
    const int mh   = w >> 2,   nw   = w & 3;
    const int g    = lane >> 2, qi  = lane & 3;

    // ldmatrix per-lane source rows/cols
    const int arof = (lane & 7) + ((lane >> 3) & 1) * 8;
    const int acof = (lane >> 4) * 8;
    const int brof = lane & 7;
    const int bcof = ((lane >> 3) & 1) * 8 + (lane >> 4) * 64;

    const u32 sbA = (u32)__cvta_generic_to_shared(As);
    const u32 sbC = (u32)__cvta_generic_to_shared(Cs);
    u32 apt[4], bpt[2];
#pragma unroll
    for (int mt = 0; mt < 4; mt++)
        apt[mt] = sbA + (u32)(((mh * 64 + mt * 16 + arof) * PAD + acof) * 2);
#pragma unroll
    for (int nt = 0; nt < 2; nt++)
        bpt[nt] = sbC + (u32)(((nw * 16 + nt * 8 + brof) * PAD + bcof) * 2);

    float acc[4][2][4];
#pragma unroll
    for (int mt = 0; mt < 4; mt++)
#pragma unroll
        for (int nt = 0; nt < 2; nt++)
#pragma unroll
            for (int q = 0; q < 4; q++) acc[mt][nt][q] = 0.0f;

#pragma unroll 1
    for (int kq = 0; kq < 4; kq++) {
        const u32 kb = (u32)kq * 32;                  // 16 bf16 per K-step
        u32 bH[2][2], bL[2][2];
#pragma unroll
        for (int nt = 0; nt < 2; nt++)
            ldsm4(bH[nt][0], bH[nt][1], bL[nt][0], bL[nt][1], bpt[nt] + kb);

#pragma unroll
        for (int p2 = 0; p2 < 2; p2++) {              // mt pair {2p2, 2p2+1}
            u32 af[2][4];
#pragma unroll
            for (int m2 = 0; m2 < 2; m2++)            // Ah fragments
                ldsm4(af[m2][0], af[m2][1], af[m2][2], af[m2][3],
                      apt[2 * p2 + m2] + kb);
#pragma unroll
            for (int nt = 0; nt < 2; nt++)
#pragma unroll
                for (int m2 = 0; m2 < 2; m2++)
                    mma16816(acc[2 * p2 + m2][nt], af[m2], bH[nt][0], bH[nt][1]); // Ah*Ch
#pragma unroll
            for (int nt = 0; nt < 2; nt++)
#pragma unroll
                for (int m2 = 0; m2 < 2; m2++)
                    mma16816(acc[2 * p2 + m2][nt], af[m2], bL[nt][0], bL[nt][1]); // Ah*Cl
#pragma unroll
            for (int m2 = 0; m2 < 2; m2++)            // Al fragments (reuse regs)
                ldsm4(af[m2][0], af[m2][1], af[m2][2], af[m2][3],
                      apt[2 * p2 + m2] + kb + 128);   // +64 bf16
#pragma unroll
            for (int nt = 0; nt < 2; nt++)
#pragma unroll
                for (int m2 = 0; m2 < 2; m2++)
                    mma16816(acc[2 * p2 + m2][nt], af[m2], bH[nt][0], bH[nt][1]); // Al*Ch
        }
    }

    // --- epilogue: direct STG.32; each quad-row hits one exact 32B sector ---
    float* ob = out + (size_t)a * NS + (size_t)(nh * 64 + nw * 16) * 128;
#pragma unroll
    for (int nt = 0; nt < 2; nt++)
#pragma unroll
        for (int mt = 0; mt < 4; mt++) {
            float* b = ob + (size_t)(nt * 8 + 2 * qi) * 128 + mh * 64 + mt * 16 + g;
            b[0]   = acc[mt][nt][0];
            b[128] = acc[mt][nt][1];
            b[8]   = acc[mt][nt][2];
            b[136] = acc[mt][nt][3];
        }
}

// ---------------------------------------------------------------------------
extern "C" void kernel_launch(void* const* d_in, const int* in_sizes, int n_in,
                              void* d_out, int out_size)
{
    const float* osc   = (const float*)d_in[0];
    const float* amp   = (const float*)d_in[1];
    const float* decay = (const float*)d_in[2];

    int A = in_sizes[0] / FR;

    cudaFuncSetAttribute(synth_mma_kernel,
                         cudaFuncAttributeMaxDynamicSharedMemorySize, SM_TOTAL);
    dim3 grid(A, 4);
    synth_mma_kernel<<<grid, TPB, SM_TOTAL>>>(osc, amp, decay, (float*)d_out);
}

// round 16
// speedup vs baseline: 1.0045x; 1.0045x over previous
#include <cuda_runtime.h>
#include <cuda_bf16.h>
#include <math.h>

// Fixed shape: A=128 atoms, FR=16 partials, NS=32768 samples, NF=128 frames.
// t = 128*T + tau, T in [0,256), tau in [0,128).
// out[a, 128T+tau] = Ah*Ch + Al*Ch + Ah*Cl (hi/lo bf16 split).
// CTA = (atom, T-quarter): grid (128, 4), one wave at 4 CTAs/SM.
// Tail quarters (nh>=2): decay factor <= d^64 <= 4.6e-3 for ALL valid inputs
// (decay in [0,1) -> d <= 0.9193), so the lo-correction products change the
// global rel err by < 2e-5 there -> single-product Ah*Ch path (1/3 the MMAs,
// <1/2 the LDSM wavefronts).
#define FR   16
#define NS   32768
#define TPB  256
#define PAD  136                    // bf16 per smem row (128+8); 68 words = 4 mod 32

#define TURN2RAD 1.4629180792671596e-9f   // 2*pi / 2^32

// smem layout (bytes)
#define SM_PAR 0                    // float4[16]
#define SM_A   256                  // bf16[128*136] = 34816  {Ah | Al}
#define SM_C   35072                // bf16[ 64*136] = 17408  {Ch | Cl}
#define SM_TOTAL 52480

typedef unsigned u32;

static __device__ __forceinline__ void mma16816(float* d, const u32* a, u32 b0, u32 b1) {
    asm volatile(
        "mma.sync.aligned.m16n8k16.row.col.f32.bf16.bf16.f32 "
        "{%0,%1,%2,%3}, {%4,%5,%6,%7}, {%8,%9}, {%0,%1,%2,%3};"
        : "+f"(d[0]), "+f"(d[1]), "+f"(d[2]), "+f"(d[3])
        : "r"(a[0]), "r"(a[1]), "r"(a[2]), "r"(a[3]), "r"(b0), "r"(b1));
}

static __device__ __forceinline__ void ldsm4(u32& r0, u32& r1, u32& r2, u32& r3, u32 addr) {
    asm volatile("ldmatrix.sync.aligned.m8n8.x4.shared.b16 {%0,%1,%2,%3}, [%4];"
                 : "=r"(r0), "=r"(r1), "=r"(r2), "=r"(r3) : "r"(addr));
}
static __device__ __forceinline__ void ldsm2(u32& r0, u32& r1, u32 addr) {
    asm volatile("ldmatrix.sync.aligned.m8n8.x2.shared.b16 {%0,%1}, [%2];"
                 : "=r"(r0), "=r"(r1) : "r"(addr));
}

// pack {bf16(a), bf16(b)} into a u32
static __device__ __forceinline__ u32 pkbf(float a, float b) {
    u32 r;
    asm("cvt.rn.bf16x2.f32 %0, %2, %1;" : "=r"(r) : "f"(a), "f"(b));
    return r;
}
static __device__ __forceinline__ float lo16f(u32 v) {
    return __bfloat162float(__ushort_as_bfloat16((unsigned short)(v & 0xFFFF)));
}
static __device__ __forceinline__ float hi16f(u32 v) {
    return __bfloat162float(__ushort_as_bfloat16((unsigned short)(v >> 16)));
}

// ---------------------------------------------------------------------------
__global__ void __launch_bounds__(TPB, 4)
synth_mma_kernel(const float* __restrict__ osc,
                 const float* __restrict__ amp,
                 const float* __restrict__ decay,
                 float* __restrict__ out)
{
    extern __shared__ char smem[];
    float4*        par = (float4*)(smem + SM_PAR);    // {phi bits, P, d, log2 d}
    __nv_bfloat16* As  = (__nv_bfloat16*)(smem + SM_A);
    __nv_bfloat16* Cs  = (__nv_bfloat16*)(smem + SM_C);

    const int tid  = threadIdx.x;
    const int a    = blockIdx.x;
    const int nh   = blockIdx.y;                      // T-quarter: T = nh*64 + Tl
    const bool full = (nh < 2);                       // hi/lo correction needed?

    // --- per-partial params (replicate reference fp32 rounding chain) ---
    if (tid < FR) {
        int i = a * FR + tid;
        float o   = osc[i];
        float sgf = (float)(1.0 / (1.0 + exp(-(double)o)));
        float fq  = (sgf * sgf) * 3.14159274101257324219f;     // fl32(pi)
        double f2p = (double)fq * (1.0 / (2.0 * M_PI));
        u32 phi = (u32)llrint(f2p * 4294967296.0);             // Q0.32 turns/sample

        float am = amp[i];
        float P  = am * am * 0.0625f;

        float dv  = decay[i];
        float sgd = (float)(1.0 / (1.0 + exp(-(double)dv)));
        float d   = 0.7f + sgd * 0.299999f;
        float l2d = (float)log2((double)d);
        par[tid] = make_float4(__uint_as_float(phi), P, d, l2d);
    }
    __syncthreads();

    // --- A (basis) tile: f-major items, packed STS.64, conflict-free ---
    for (int idx = tid; idx < FR * 128; idx += TPB) {
        int f = idx & 15, tau = idx >> 4;
        u32 phi = __float_as_uint(par[f].x);
        u32 p   = (u32)tau * phi;
        float x = (float)(int)p * TURN2RAD;
        float s = __sinf(x), c = __cosf(x);
        float ts = (float)tau * 0.0078125f;
        float v0 = s, v1 = c, v2 = s * ts, v3 = c * ts;

        u32 h01 = pkbf(v0, v1), h23 = pkbf(v2, v3);
        __nv_bfloat16* row = As + tau * PAD + 4 * f;
        *(uint2*)(row) = make_uint2(h01, h23);         // Ah
        if (full) {
            u32 l01 = pkbf(v0 - lo16f(h01), v1 - hi16f(h01));
            u32 l23 = pkbf(v2 - lo16f(h23), v3 - hi16f(h23));
            *(uint2*)(row + 64) = make_uint2(l01, l23);   // Al
        }
    }

    // --- C (coefficient) tile: f-major, packed STS.64 ---
    for (int idx = tid; idx < FR * 64; idx += TPB) {
        int f = idx & 15, Tl = idx >> 4;
        int T = nh * 64 + Tl;
        float4 pr = par[f];
        u32 phi = __float_as_uint(pr.x);
        float P = pr.y, d = pr.z, l2d = pr.w;

        float al, be;
        if (T == 0)        { al = exp2f(l2d);          be = 0.0f; }
        else if (T == 255) { al = exp2f(128.0f * l2d); be = 0.0f; }
        else {
            int   i0 = (T - 1) >> 1;
            float w0 = (T & 1) ? 0.001953125f : 0.501953125f;
            float dj = exp2f((float)(i0 + 1) * l2d);   // d^(i0+1)
            float dm1 = d - 1.0f;
            al = dj * fmaf(w0, dm1, 1.0f);
            be = dj * dm1 * 0.5f;              // coefficient of ts = tau/128
        }
        u32 p   = (u32)(128 * T + 1) * phi;
        float x = (float)(int)p * TURN2RAD;
        float SA = __sinf(x), CA = __cosf(x);
        float Pal = P * al, Pbe = P * be;
        float e0 = Pal * CA, e1 = Pal * SA, e2 = Pbe * CA, e3 = Pbe * SA;

        u32 h01 = pkbf(e0, e1), h23 = pkbf(e2, e3);
        __nv_bfloat16* row = Cs + Tl * PAD + 4 * f;
        *(uint2*)(row) = make_uint2(h01, h23);         // Ch
        if (full) {
            u32 l01 = pkbf(e0 - lo16f(h01), e1 - hi16f(h01));
            u32 l23 = pkbf(e2 - lo16f(h23), e3 - hi16f(h23));
            *(uint2*)(row + 64) = make_uint2(l01, l23);   // Cl
        }
    }
    __syncthreads();

    // --- MMA: D[128 tau x 64 Tl]. warp = (mh tau-half, nw 16-T stripe). ---
    const int w    = tid >> 5, lane = tid & 31;
    const int mh   = w >> 2,   nw   = w & 3;
    const int g    = lane >> 2, qi  = lane & 3;

    const int arof = (lane & 7) + ((lane >> 3) & 1) * 8;
    const int acof = (lane >> 4) * 8;
    const int brof = lane & 7;
    const int bcof = ((lane >> 3) & 1) * 8 + (lane >> 4) * 64;

    const u32 sbA = (u32)__cvta_generic_to_shared(As);
    const u32 sbC = (u32)__cvta_generic_to_shared(Cs);
    u32 apt[4], bpt[2];
#pragma unroll
    for (int mt = 0; mt < 4; mt++)
        apt[mt] = sbA + (u32)(((mh * 64 + mt * 16 + arof) * PAD + acof) * 2);
#pragma unroll
    for (int nt = 0; nt < 2; nt++)
        bpt[nt] = sbC + (u32)(((nw * 16 + nt * 8 + brof) * PAD + bcof) * 2);

    float acc[4][2][4];
#pragma unroll
    for (int mt = 0; mt < 4; mt++)
#pragma unroll
        for (int nt = 0; nt < 2; nt++)
#pragma unroll
            for (int q = 0; q < 4; q++) acc[mt][nt][q] = 0.0f;

    if (full) {
        // ---- 3-product path (T < 128) ----
#pragma unroll 1
        for (int kq = 0; kq < 4; kq++) {
            const u32 kb = (u32)kq * 32;
            u32 bH[2][2], bL[2][2];
#pragma unroll
            for (int nt = 0; nt < 2; nt++)
                ldsm4(bH[nt][0], bH[nt][1], bL[nt][0], bL[nt][1], bpt[nt] + kb);
#pragma unroll
            for (int p2 = 0; p2 < 2; p2++) {
                u32 af[2][4];
#pragma unroll
                for (int m2 = 0; m2 < 2; m2++)
                    ldsm4(af[m2][0], af[m2][1], af[m2][2], af[m2][3],
                          apt[2 * p2 + m2] + kb);
#pragma unroll
                for (int nt = 0; nt < 2; nt++)
#pragma unroll
                    for (int m2 = 0; m2 < 2; m2++)
                        mma16816(acc[2 * p2 + m2][nt], af[m2], bH[nt][0], bH[nt][1]);
#pragma unroll
                for (int nt = 0; nt < 2; nt++)
#pragma unroll
                    for (int m2 = 0; m2 < 2; m2++)
                        mma16816(acc[2 * p2 + m2][nt], af[m2], bL[nt][0], bL[nt][1]);
#pragma unroll
                for (int m2 = 0; m2 < 2; m2++)
                    ldsm4(af[m2][0], af[m2][1], af[m2][2], af[m2][3],
                          apt[2 * p2 + m2] + kb + 128);
#pragma unroll
                for (int nt = 0; nt < 2; nt++)
#pragma unroll
                    for (int m2 = 0; m2 < 2; m2++)
                        mma16816(acc[2 * p2 + m2][nt], af[m2], bH[nt][0], bH[nt][1]);
            }
        }
    } else {
        // ---- single-product path (T >= 128; decayed tail) ----
#pragma unroll 1
        for (int kq = 0; kq < 4; kq++) {
            const u32 kb = (u32)kq * 32;
            u32 bH[2][2];
#pragma unroll
            for (int nt = 0; nt < 2; nt++)
                ldsm2(bH[nt][0], bH[nt][1], bpt[nt] + kb);
#pragma unroll
            for (int p2 = 0; p2 < 2; p2++) {
                u32 af[2][4];
#pragma unroll
                for (int m2 = 0; m2 < 2; m2++)
                    ldsm4(af[m2][0], af[m2][1], af[m2][2], af[m2][3],
                          apt[2 * p2 + m2] + kb);
#pragma unroll
                for (int nt = 0; nt < 2; nt++)
#pragma unroll
                    for (int m2 = 0; m2 < 2; m2++)
                        mma16816(acc[2 * p2 + m2][nt], af[m2], bH[nt][0], bH[nt][1]);
            }
        }
    }

    // --- epilogue: direct STG.32; each quad-row hits one exact 32B sector ---
    float* ob = out + (size_t)a * NS + (size_t)(nh * 64 + nw * 16) * 128;
#pragma unroll
    for (int nt = 0; nt < 2; nt++)
#pragma unroll
        for (int mt = 0; mt < 4; mt++) {
            float* b = ob + (size_t)(nt * 8 + 2 * qi) * 128 + mh * 64 + mt * 16 + g;
            b[0]   = acc[mt][nt][0];
            b[128] = acc[mt][nt][1];
            b[8]   = acc[mt][nt][2];
            b[136] = acc[mt][nt][3];
        }
}

// ---------------------------------------------------------------------------
extern "C" void kernel_launch(void* const* d_in, const int* in_sizes, int n_in,
                              void* d_out, int out_size)
{
    const float* osc   = (const float*)d_in[0];
    const float* amp   = (const float*)d_in[1];
    const float* decay = (const float*)d_in[2];

    int A = in_sizes[0] / FR;

    cudaFuncSetAttribute(synth_mma_kernel,
                         cudaFuncAttributeMaxDynamicSharedMemorySize, SM_TOTAL);
    dim3 grid(A, 4);
    synth_mma_kernel<<<grid, TPB, SM_TOTAL>>>(osc, amp, decay, (float*)d_out);
}

// round 17
// speedup vs baseline: 1.1873x; 1.1821x over previous
#include <cuda_runtime.h>
#include <cuda_fp16.h>
#include <math.h>

// Fixed shape: A=128 atoms, FR=16 partials, NS=32768 samples, NF=128 frames.
// t = 128*T + tau, T in [0,256), tau in [0,128).
// out[a, 128T+tau] = A[tau,k] * C[T,k] over K=64, SINGLE fp16 product
// (fp16 mantissa 10 bits -> per-element ~2.4e-4 rms; output adds ~3e-4 in
// quadrature to the 4.36e-4 reference-phase floor -> ~5.3e-4, under 1e-3).
// CTA = (atom, T-quarter): grid (128, 4), one balanced wave at 4 CTAs/SM.
#define FR   16
#define NS   32768
#define TPB  256
#define PADA 72                     // fp16 per smem row (64+8); 36 words = 4 mod 32

#define TURN2RAD 1.4629180792671596e-9f   // 2*pi / 2^32

// smem layout (bytes)
#define SM_PAR 0                    // float4[16]
#define SM_A   256                  // fp16[128*72] = 18432
#define SM_C   18688                // fp16[ 64*72] =  9216
#define SM_TOTAL 27904

typedef unsigned u32;

static __device__ __forceinline__ void mma16816(float* d, const u32* a, u32 b0, u32 b1) {
    asm volatile(
        "mma.sync.aligned.m16n8k16.row.col.f32.f16.f16.f32 "
        "{%0,%1,%2,%3}, {%4,%5,%6,%7}, {%8,%9}, {%0,%1,%2,%3};"
        : "+f"(d[0]), "+f"(d[1]), "+f"(d[2]), "+f"(d[3])
        : "r"(a[0]), "r"(a[1]), "r"(a[2]), "r"(a[3]), "r"(b0), "r"(b1));
}

static __device__ __forceinline__ void ldsm4(u32& r0, u32& r1, u32& r2, u32& r3, u32 addr) {
    asm volatile("ldmatrix.sync.aligned.m8n8.x4.shared.b16 {%0,%1,%2,%3}, [%4];"
                 : "=r"(r0), "=r"(r1), "=r"(r2), "=r"(r3) : "r"(addr));
}

// pack {fp16(a) lo, fp16(b) hi} into a u32
static __device__ __forceinline__ u32 pk16(float a, float b) {
    u32 r;
    asm("cvt.rn.f16x2.f32 %0, %2, %1;" : "=r"(r) : "f"(a), "f"(b));
    return r;
}

// ---------------------------------------------------------------------------
__global__ void __launch_bounds__(TPB, 4)
synth_mma_kernel(const float* __restrict__ osc,
                 const float* __restrict__ amp,
                 const float* __restrict__ decay,
                 float* __restrict__ out)
{
    extern __shared__ char smem[];
    float4* par = (float4*)(smem + SM_PAR);           // {phi bits, P, d, log2 d}
    __half* As  = (__half*)(smem + SM_A);
    __half* Cs  = (__half*)(smem + SM_C);

    const int tid = threadIdx.x;
    const int a   = blockIdx.x;
    const int nh  = blockIdx.y;                       // T-quarter: T = nh*64 + Tl

    // --- per-partial params (replicate reference fp32 rounding chain) ---
    if (tid < FR) {
        int i = a * FR + tid;
        float o   = osc[i];
        float sgf = (float)(1.0 / (1.0 + exp(-(double)o)));
        float fq  = (sgf * sgf) * 3.14159274101257324219f;     // fl32(pi)
        double f2p = (double)fq * (1.0 / (2.0 * M_PI));
        u32 phi = (u32)llrint(f2p * 4294967296.0);             // Q0.32 turns/sample

        float am = amp[i];
        float P  = am * am * 0.0625f;

        float dv  = decay[i];
        float sgd = (float)(1.0 / (1.0 + exp(-(double)dv)));
        float d   = 0.7f + sgd * 0.299999f;
        float l2d = (float)log2((double)d);
        par[tid] = make_float4(__uint_as_float(phi), P, d, l2d);
    }
    __syncthreads();

    // --- A (basis) tile: f-major items, one STS.64 each, conflict-floor ---
    for (int idx = tid; idx < FR * 128; idx += TPB) {
        int f = idx & 15, tau = idx >> 4;
        u32 phi = __float_as_uint(par[f].x);
        u32 p   = (u32)tau * phi;
        float x = (float)(int)p * TURN2RAD;
        float s = __sinf(x), c = __cosf(x);
        float ts = (float)tau * 0.0078125f;
        *(uint2*)(As + tau * PADA + 4 * f) =
            make_uint2(pk16(s, c), pk16(s * ts, c * ts));
    }

    // --- C (coefficient) tile: 64 local T rows, f-major ---
    for (int idx = tid; idx < FR * 64; idx += TPB) {
        int f = idx & 15, Tl = idx >> 4;
        int T = nh * 64 + Tl;
        float4 pr = par[f];
        u32 phi = __float_as_uint(pr.x);
        float P = pr.y, d = pr.z, l2d = pr.w;

        float al, be;
        if (T == 0)        { al = exp2f(l2d);          be = 0.0f; }
        else if (T == 255) { al = exp2f(128.0f * l2d); be = 0.0f; }
        else {
            int   i0 = (T - 1) >> 1;
            float w0 = (T & 1) ? 0.001953125f : 0.501953125f;
            float dj = exp2f((float)(i0 + 1) * l2d);   // d^(i0+1)
            float dm1 = d - 1.0f;
            al = dj * fmaf(w0, dm1, 1.0f);
            be = dj * dm1 * 0.5f;              // coefficient of ts = tau/128
        }
        u32 p   = (u32)(128 * T + 1) * phi;
        float x = (float)(int)p * TURN2RAD;
        float SA = __sinf(x), CA = __cosf(x);
        float Pal = P * al, Pbe = P * be;
        *(uint2*)(Cs + Tl * PADA + 4 * f) =
            make_uint2(pk16(Pal * CA, Pal * SA), pk16(Pbe * CA, Pbe * SA));
    }
    __syncthreads();

    // --- MMA: D[128 tau x 64 Tl]. warp = (mh tau-half, nw 16-T stripe). ---
    const int w    = tid >> 5, lane = tid & 31;
    const int mh   = w >> 2,   nw   = w & 3;
    const int g    = lane >> 2, qi  = lane & 3;

    // A fragment lanes: mats {r,k0},{r+8,k0},{r,k8},{r+8,k8}
    const int arof = (lane & 7) + ((lane >> 3) & 1) * 8;
    const int acof = (lane >> 4) * 8;
    // B quad lanes: mats {nt0,k0},{nt0,k8},{nt1,k0},{nt1,k8}
    const int brof = (lane & 7) + ((lane >> 4) & 1) * 8;
    const int bcof = ((lane >> 3) & 1) * 8;

    const u32 sbA = (u32)__cvta_generic_to_shared(As);
    const u32 sbC = (u32)__cvta_generic_to_shared(Cs);
    u32 apt[4];
#pragma unroll
    for (int mt = 0; mt < 4; mt++)
        apt[mt] = sbA + (u32)(((mh * 64 + mt * 16 + arof) * PADA + acof) * 2);
    const u32 bpt = sbC + (u32)(((nw * 16 + brof) * PADA + bcof) * 2);

    float acc[4][2][4];
#pragma unroll
    for (int mt = 0; mt < 4; mt++)
#pragma unroll
        for (int nt = 0; nt < 2; nt++)
#pragma unroll
            for (int q = 0; q < 4; q++) acc[mt][nt][q] = 0.0f;

#pragma unroll 1
    for (int kq = 0; kq < 4; kq++) {
        const u32 kb = (u32)kq * 32;                  // 16 fp16 = 32 B per K-step
        u32 b00, b01, b10, b11;
        ldsm4(b00, b01, b10, b11, bpt + kb);          // both nt tiles, one LDSM
        u32 af[4][4];
#pragma unroll
        for (int mt = 0; mt < 4; mt++)
            ldsm4(af[mt][0], af[mt][1], af[mt][2], af[mt][3], apt[mt] + kb);
#pragma unroll
        for (int mt = 0; mt < 4; mt++) {
            mma16816(acc[mt][0], af[mt], b00, b01);
            mma16816(acc[mt][1], af[mt], b10, b11);
        }
    }

    // --- epilogue: direct STG.32; each quad-row hits one exact 32B sector ---
    float* ob = out + (size_t)a * NS + (size_t)(nh * 64 + nw * 16) * 128;
#pragma unroll
    for (int nt = 0; nt < 2; nt++)
#pragma unroll
        for (int mt = 0; mt < 4; mt++) {
            float* b = ob + (size_t)(nt * 8 + 2 * qi) * 128 + mh * 64 + mt * 16 + g;
            b[0]   = acc[mt][nt][0];
            b[128] = acc[mt][nt][1];
            b[8]   = acc[mt][nt][2];
            b[136] = acc[mt][nt][3];
        }
}

// ---------------------------------------------------------------------------
extern "C" void kernel_launch(void* const* d_in, const int* in_sizes, int n_in,
                              void* d_out, int out_size)
{
    const float* osc   = (const float*)d_in[0];
    const float* amp   = (const float*)d_in[1];
    const float* decay = (const float*)d_in[2];

    int A = in_sizes[0] / FR;

    cudaFuncSetAttribute(synth_mma_kernel,
                         cudaFuncAttributeMaxDynamicSharedMemorySize, SM_TOTAL);
    dim3 grid(A, 4);
    synth_mma_kernel<<<grid, TPB, SM_TOTAL>>>(osc, amp, decay, (float*)d_out);
}